// round 16
// baseline (speedup 1.0000x reference)
#include <cuda_runtime.h>
#include <math.h>

#define BB 128
#define SS 512
#define HH 1024

typedef unsigned long long ull;

// ---------------- scratch (device globals: no allocation allowed) ----------
__device__ float g_XB[(size_t)BB * SS * HH];     // x @ Bm^T
__device__ float g_G [(size_t)BB * SS * HH];     // sigmoid(x @ Wg^T + bg)
__device__ float g_Sbuf[(size_t)BB * SS * HH];   // all states s_t, (b, t, h)
__device__ float g_sT[2][HH][BB];                // k-major state, ping-pong
__device__ unsigned g_cnt[8 * 32];               // group arrival counters
__device__ unsigned g_master;                    // group-completion counter
__device__ unsigned g_gen;                       // published generation

// ---------------- packed f32x2 helpers (bitwise == 2x scalar IEEE-rn) ------
__device__ __forceinline__ ull pack2(float lo, float hi) {
    ull r; asm("mov.b64 %0, {%1, %2};" : "=l"(r) : "f"(lo), "f"(hi)); return r;
}
__device__ __forceinline__ void unpack2(ull v, float& lo, float& hi) {
    asm("mov.b64 {%0, %1}, %2;" : "=f"(lo), "=f"(hi) : "l"(v));
}
__device__ __forceinline__ void fma2(ull& d, ull a, ull b) {
    asm("fma.rn.f32x2 %0, %1, %2, %0;" : "+l"(d) : "l"(a), "l"(b));
}
__device__ __forceinline__ ull add2(ull a, ull b) {
    ull d; asm("add.rn.f32x2 %0, %1, %2;" : "=l"(d) : "l"(a), "l"(b)); return d;
}

// ---------------- two-level grid barrier (128 CTAs resident) ---------------
__device__ __forceinline__ void gsync(int bid, unsigned& gen) {
    __syncthreads();
    gen += 1;
    if (threadIdx.x == 0) {
        __threadfence();                                   // release my writes
        unsigned r = atomicAdd(&g_cnt[(bid & 7) * 32], 1u);
        if ((r & 15u) == 15u) {
            unsigned m = atomicAdd(&g_master, 1u);
            if ((m & 7u) == 7u)
                atomicExch(&g_gen, gen);
        }
        while ((int)(*(volatile unsigned*)&g_gen - gen) < 0) { }
        __threadfence();                                   // acquire
    }
    __syncthreads();
}

// ---------------- SGEMM v3 (proven): out[m,n] = sum_k X[m,k]*W[n,k] --------
// 128x64 tile, 8x4 micro (row-paired f32x2 accumulators), BK=16,
// double-buffered SMEM. Numerics: per output, k-ascending FMA chain with
// kc=512 panel split, result = add.rn(chain_lo, chain_hi) — bitwise == r10.
// EPI==1: sigmoid(acc + bias[n]) via 1/(1+expf(-x)).
template <int EPI>
__global__ __launch_bounds__(256, 2) void sgemm_nt(
    const float* __restrict__ X, const float* __restrict__ W,
    const float* __restrict__ bias, float* __restrict__ out,
    int M, int N, int K)
{
    __shared__ __align__(16) float Xs[2][16][132];
    __shared__ __align__(16) float Ws[2][16][68];

    const int n0 = blockIdx.x * 64;
    const int m0 = blockIdx.y * 128;
    const int tid = threadIdx.x;
    const int tx = tid & 15;            // 16 col-groups of 4
    const int ty = tid >> 4;            // 16 row-groups of 8

    const int srow = tid >> 2;          // 0..63
    const int skq  = (tid & 3) * 4;     // 0,4,8,12
    const float* Xp0 = X + (size_t)(m0 + srow) * K + skq;
    const float* Xp1 = X + (size_t)(m0 + srow + 64) * K + skq;
    const float* Wp  = W + (size_t)(n0 + srow) * K + skq;

    ull acc2[4][4], accL2[4][4];
#pragma unroll
    for (int u = 0; u < 4; u++)
#pragma unroll
        for (int j = 0; j < 4; j++) { acc2[u][j] = 0ull; accL2[u][j] = 0ull; }

    float4 xv0 = *reinterpret_cast<const float4*>(Xp0);
    float4 xv1 = *reinterpret_cast<const float4*>(Xp1);
    float4 wv  = *reinterpret_cast<const float4*>(Wp);
    Xs[0][skq + 0][srow] = xv0.x; Xs[0][skq + 1][srow] = xv0.y;
    Xs[0][skq + 2][srow] = xv0.z; Xs[0][skq + 3][srow] = xv0.w;
    Xs[0][skq + 0][srow + 64] = xv1.x; Xs[0][skq + 1][srow + 64] = xv1.y;
    Xs[0][skq + 2][srow + 64] = xv1.z; Xs[0][skq + 3][srow + 64] = xv1.w;
    Ws[0][skq + 0][srow] = wv.x; Ws[0][skq + 1][srow] = wv.y;
    Ws[0][skq + 2][srow] = wv.z; Ws[0][skq + 3][srow] = wv.w;
    __syncthreads();

    const int ntiles = K / 16;          // 64
#pragma unroll 1
    for (int it = 0; it < ntiles; it++) {
        const int buf = it & 1;
        if (it + 1 < ntiles) {
            xv0 = *reinterpret_cast<const float4*>(Xp0 + (it + 1) * 16);
            xv1 = *reinterpret_cast<const float4*>(Xp1 + (it + 1) * 16);
            wv  = *reinterpret_cast<const float4*>(Wp  + (it + 1) * 16);
        }
#pragma unroll
        for (int k = 0; k < 16; k++) {  // k strictly ascending
            const ulonglong2* ap =
                reinterpret_cast<const ulonglong2*>(&Xs[buf][k][ty * 8]);
            ulonglong2 a01 = ap[0];
            ulonglong2 a23 = ap[1];
            float4 b = *reinterpret_cast<const float4*>(&Ws[buf][k][tx * 4]);
            ull b2[4] = {pack2(b.x, b.x), pack2(b.y, b.y),
                         pack2(b.z, b.z), pack2(b.w, b.w)};
            ull a2[4] = {a01.x, a01.y, a23.x, a23.y};
#pragma unroll
            for (int u = 0; u < 4; u++)
#pragma unroll
                for (int j = 0; j < 4; j++)
                    fma2(acc2[u][j], a2[u], b2[j]);
        }
        if ((it + 1) * 16 == 512) {     // kc=512 panel boundary
#pragma unroll
            for (int u = 0; u < 4; u++)
#pragma unroll
                for (int j = 0; j < 4; j++) { accL2[u][j] = acc2[u][j]; acc2[u][j] = 0ull; }
        }
        if (it + 1 < ntiles) {
            const int nb = buf ^ 1;
            Xs[nb][skq + 0][srow] = xv0.x; Xs[nb][skq + 1][srow] = xv0.y;
            Xs[nb][skq + 2][srow] = xv0.z; Xs[nb][skq + 3][srow] = xv0.w;
            Xs[nb][skq + 0][srow + 64] = xv1.x; Xs[nb][skq + 1][srow + 64] = xv1.y;
            Xs[nb][skq + 2][srow + 64] = xv1.z; Xs[nb][skq + 3][srow + 64] = xv1.w;
            Ws[nb][skq + 0][srow] = wv.x; Ws[nb][skq + 1][srow] = wv.y;
            Ws[nb][skq + 2][srow] = wv.z; Ws[nb][skq + 3][srow] = wv.w;
        }
        __syncthreads();
    }

    float bv[4];
    if (EPI == 1) {
#pragma unroll
        for (int j = 0; j < 4; j++) bv[j] = bias[n0 + tx * 4 + j];
    }
#pragma unroll
    for (int u = 0; u < 4; u++) {
        float lo[4], hi[4];
#pragma unroll
        for (int j = 0; j < 4; j++) {
            ull s2 = add2(accL2[u][j], acc2[u][j]);   // add(chain_lo, chain_hi)
            unpack2(s2, lo[j], hi[j]);
            if (EPI == 1) {
                lo[j] = 1.f / (1.f + expf(-(lo[j] + bv[j])));
                hi[j] = 1.f / (1.f + expf(-(hi[j] + bv[j])));
            }
        }
        float4 o0; o0.x = lo[0]; o0.y = lo[1]; o0.z = lo[2]; o0.w = lo[3];
        float4 o1; o1.x = hi[0]; o1.y = hi[1]; o1.z = hi[2]; o1.w = hi[3];
        *reinterpret_cast<float4*>(
            out + (size_t)(m0 + ty * 8 + 2 * u) * N + n0 + tx * 4) = o0;
        *reinterpret_cast<float4*>(
            out + (size_t)(m0 + ty * 8 + 2 * u + 1) * N + n0 + tx * 4) = o1;
    }
}

// ---------------- persistent scan kernel (r13 structure, f32x2 core) -------
// grid = 128 CTAs x 256 threads. CTA owns 8 output channels h0..h0+7.
// thread: m = tid&127 (batch row), half = tid>>7 (k-split: 512 k each).
// dotA = add(chain(k<512), chain(k>=512)); channel-paired f32x2 accumulators
// (per-channel chain order == scalar, bitwise == r10); scalar state loads,
// 8-deep prefetch (proven best depth).
__global__ __launch_bounds__(256) void scan_kernel(
    const float* __restrict__ state0, const float* __restrict__ A,
    const float* __restrict__ log_dt,
    const float* __restrict__ XB, const float* __restrict__ G,
    float* __restrict__ Sbuf, float* __restrict__ out_state)
{
    __shared__ __align__(16) float As[HH][8];   // As[k][j] = A[h0+j][k]
    __shared__ float Rs[BB][9];                 // half-1 partial sums (pad 9)

    const int tid  = threadIdx.x;
    const int bid  = blockIdx.x;
    const int h0   = bid * 8;
    const int m    = tid & 127;
    const int half = tid >> 7;
    const int kbase = half * 512;

    for (int idx = tid; idx < 8 * HH; idx += 256) {
        int j = idx >> 10, k = idx & 1023;
        As[k][j] = A[(size_t)(h0 + j) * HH + k];
    }
    if (tid < BB) {
#pragma unroll
        for (int j = 0; j < 8; j++)
            g_sT[0][h0 + j][tid] = state0[(size_t)tid * HH + h0 + j];
    }

    float dt[8], sreg[8];
    if (half == 0) {
#pragma unroll
        for (int j = 0; j < 8; j++) {
            float d = expf(log_dt[h0 + j]);
            dt[j] = fminf(fmaxf(d, 0.001f), 0.1f);
            sreg[j] = state0[(size_t)m * HH + h0 + j];
        }
    }

    unsigned gen = *(volatile unsigned*)&g_gen;
    gsync(bid, gen);

    const float* sbase = &g_sT[0][0][0];

    for (int t = 0; t < SS; t++) {
        const int cur = t & 1;
        const int nxt = cur ^ 1;

        float4 xb0, xb1, gg0, gg1;
        size_t rowbase = ((size_t)m * SS + t) * HH + h0;
        if (half == 0) {
            xb0 = *reinterpret_cast<const float4*>(XB + rowbase);
            xb1 = *reinterpret_cast<const float4*>(XB + rowbase + 4);
            gg0 = *reinterpret_cast<const float4*>(G + rowbase);
            gg1 = *reinterpret_cast<const float4*>(G + rowbase + 4);
        }

        // single k-ascending chain over this thread's 512-k half,
        // 8-deep prefetch, channel-paired f32x2 accumulation.
        ull acc2[4] = {0ull, 0ull, 0ull, 0ull};
        const float* sp = sbase + (size_t)cur * HH * BB + (size_t)kbase * BB + m;

        float sv[8];
#pragma unroll
        for (int u = 0; u < 8; u++)
            sv[u] = __ldcg(sp + (size_t)u * BB);

#pragma unroll 1
        for (int kk = 0; kk < 512; kk += 8) {
            float nv[8];
            if (kk + 8 < 512) {
#pragma unroll
                for (int u = 0; u < 8; u++)
                    nv[u] = __ldcg(sp + (size_t)(kk + 8 + u) * BB);
            }
#pragma unroll
            for (int u = 0; u < 8; u++) {
                ull s2 = pack2(sv[u], sv[u]);
                const ulonglong2* ap =
                    reinterpret_cast<const ulonglong2*>(&As[kbase + kk + u][0]);
                ulonglong2 a01 = ap[0];   // (ch0,ch1) (ch2,ch3)
                ulonglong2 a23 = ap[1];   // (ch4,ch5) (ch6,ch7)
                fma2(acc2[0], s2, a01.x);
                fma2(acc2[1], s2, a01.y);
                fma2(acc2[2], s2, a23.x);
                fma2(acc2[3], s2, a23.y);
            }
#pragma unroll
            for (int u = 0; u < 8; u++) sv[u] = nv[u];
        }

        float acc[8];
        unpack2(acc2[0], acc[0], acc[1]);
        unpack2(acc2[1], acc[2], acc[3]);
        unpack2(acc2[2], acc[4], acc[5]);
        unpack2(acc2[3], acc[6], acc[7]);

        if (half == 1) {
#pragma unroll
            for (int j = 0; j < 8; j++) Rs[m][j] = acc[j];
        }
        __syncthreads();

        if (half == 0) {
            float xb[8] = {xb0.x, xb0.y, xb0.z, xb0.w, xb1.x, xb1.y, xb1.z, xb1.w};
            float gv[8] = {gg0.x, gg0.y, gg0.z, gg0.w, gg1.x, gg1.y, gg1.z, gg1.w};
            float sn[8];
#pragma unroll
            for (int j = 0; j < 8; j++) {
                float dstate = acc[j] + Rs[m][j] + xb[j];   // (lo+hi)+xb
                float sc = dstate * dt[j];
                if (fabsf(sc) <= 0.1f) sc = 0.f;
                float v = sreg[j] + sc * gv[j];             // default contraction
                sreg[j] = v;
                sn[j] = v;
                g_sT[nxt][h0 + j][m] = v;
            }
            float4 o0; o0.x = sn[0]; o0.y = sn[1]; o0.z = sn[2]; o0.w = sn[3];
            float4 o1; o1.x = sn[4]; o1.y = sn[5]; o1.z = sn[6]; o1.w = sn[7];
            *reinterpret_cast<float4*>(Sbuf + rowbase)     = o0;
            *reinterpret_cast<float4*>(Sbuf + rowbase + 4) = o1;
            if (t == SS - 1 && out_state != nullptr) {
#pragma unroll
                for (int j = 0; j < 8; j++)
                    out_state[(size_t)m * HH + h0 + j] = sn[j];
            }
        }

        gsync(bid, gen);
    }
}

// ---------------- launch ----------------------------------------------------
extern "C" void kernel_launch(void* const* d_in, const int* in_sizes, int n_in,
                              void* d_out, int out_size) {
    const float* x      = (const float*)d_in[0];
    const float* state  = (const float*)d_in[1];
    const float* A      = (const float*)d_in[2];
    const float* Bm     = (const float*)d_in[3];
    const float* C      = (const float*)d_in[4];
    const float* log_dt = (const float*)d_in[5];
    const float* Wg     = (const float*)d_in[6];
    const float* bg     = (const float*)d_in[7];

    float* ys = (float*)d_out;
    const size_t ys_elems = (size_t)BB * SS * HH;
    float* out_state = nullptr;
    if ((size_t)out_size >= ys_elems + (size_t)BB * HH)
        out_state = ys + ys_elems;

    float *pXB = nullptr, *pG = nullptr, *pS = nullptr;
    cudaGetSymbolAddress((void**)&pXB, g_XB);
    cudaGetSymbolAddress((void**)&pG,  g_G);
    cudaGetSymbolAddress((void**)&pS,  g_Sbuf);

    const int M = BB * SS;            // 65536
    dim3 grid(HH / 64, M / 128);      // (16, 512), n fastest

    // off-critical-path GEMMs (kc=512 blocked chains, bitwise == round 10)
    sgemm_nt<0><<<grid, 256>>>(x, Bm, nullptr, pXB, M, HH, HH);
    sgemm_nt<1><<<grid, 256>>>(x, Wg, bg,      pG,  M, HH, HH);

    // sequential scan (persistent, 128 CTAs), f32x2 core, 8-deep prefetch
    scan_kernel<<<BB, 256>>>(state, A, log_dt, pXB, pG, pS, out_state);

    // y = Sbuf @ C^T (kc=512 blocked chains)
    sgemm_nt<0><<<grid, 256>>>(pS, C, nullptr, ys, M, HH, HH);
}

// round 17
// speedup vs baseline: 1.0542x; 1.0542x over previous
#include <cuda_runtime.h>
#include <math.h>

#define BB 128
#define SS 512
#define HH 1024

typedef unsigned long long ull;

// ---------------- scratch (device globals: no allocation allowed) ----------
__device__ float g_XB[(size_t)BB * SS * HH];     // x @ Bm^T
__device__ float g_G [(size_t)BB * SS * HH];     // sigmoid(x @ Wg^T + bg)
__device__ float g_Sbuf[(size_t)BB * SS * HH];   // all states s_t, (b, t, h)
__device__ float g_sT[2][HH][BB];                // k-major state, ping-pong
__device__ unsigned g_cnt[8 * 32];               // group arrival counters
__device__ unsigned g_master;                    // group-completion counter
__device__ unsigned g_gen;                       // published generation

// ---------------- packed f32x2 helpers (bitwise == 2x scalar IEEE-rn) ------
__device__ __forceinline__ ull pack2(float lo, float hi) {
    ull r; asm("mov.b64 %0, {%1, %2};" : "=l"(r) : "f"(lo), "f"(hi)); return r;
}
__device__ __forceinline__ void unpack2(ull v, float& lo, float& hi) {
    asm("mov.b64 {%0, %1}, %2;" : "=f"(lo), "=f"(hi) : "l"(v));
}
__device__ __forceinline__ void fma2(ull& d, ull a, ull b) {
    asm("fma.rn.f32x2 %0, %1, %2, %0;" : "+l"(d) : "l"(a), "l"(b));
}
__device__ __forceinline__ ull add2(ull a, ull b) {
    ull d; asm("add.rn.f32x2 %0, %1, %2;" : "=l"(d) : "l"(a), "l"(b)); return d;
}

// ---------------- two-level grid barrier (128 CTAs resident) ---------------
__device__ __forceinline__ void gsync(int bid, unsigned& gen) {
    __syncthreads();
    gen += 1;
    if (threadIdx.x == 0) {
        __threadfence();                                   // release my writes
        unsigned r = atomicAdd(&g_cnt[(bid & 7) * 32], 1u);
        if ((r & 15u) == 15u) {
            unsigned m = atomicAdd(&g_master, 1u);
            if ((m & 7u) == 7u)
                atomicExch(&g_gen, gen);
        }
        while ((int)(*(volatile unsigned*)&g_gen - gen) < 0) { }
        __threadfence();                                   // acquire
    }
    __syncthreads();
}

// ---------------- SGEMM v3 (proven): out[m,n] = sum_k X[m,k]*W[n,k] --------
// 128x64 tile, 8x4 micro (row-paired f32x2 accumulators), BK=16,
// double-buffered SMEM. Numerics: per output, k-ascending FMA chain with
// kc=512 panel split, result = add.rn(chain_lo, chain_hi) — bitwise == r10.
// EPI==1: sigmoid(acc + bias[n]) via 1/(1+expf(-x)).
template <int EPI>
__global__ __launch_bounds__(256, 2) void sgemm_nt(
    const float* __restrict__ X, const float* __restrict__ W,
    const float* __restrict__ bias, float* __restrict__ out,
    int M, int N, int K)
{
    __shared__ __align__(16) float Xs[2][16][132];
    __shared__ __align__(16) float Ws[2][16][68];

    const int n0 = blockIdx.x * 64;
    const int m0 = blockIdx.y * 128;
    const int tid = threadIdx.x;
    const int tx = tid & 15;            // 16 col-groups of 4
    const int ty = tid >> 4;            // 16 row-groups of 8

    const int srow = tid >> 2;          // 0..63
    const int skq  = (tid & 3) * 4;     // 0,4,8,12
    const float* Xp0 = X + (size_t)(m0 + srow) * K + skq;
    const float* Xp1 = X + (size_t)(m0 + srow + 64) * K + skq;
    const float* Wp  = W + (size_t)(n0 + srow) * K + skq;

    ull acc2[4][4], accL2[4][4];
#pragma unroll
    for (int u = 0; u < 4; u++)
#pragma unroll
        for (int j = 0; j < 4; j++) { acc2[u][j] = 0ull; accL2[u][j] = 0ull; }

    float4 xv0 = *reinterpret_cast<const float4*>(Xp0);
    float4 xv1 = *reinterpret_cast<const float4*>(Xp1);
    float4 wv  = *reinterpret_cast<const float4*>(Wp);
    Xs[0][skq + 0][srow] = xv0.x; Xs[0][skq + 1][srow] = xv0.y;
    Xs[0][skq + 2][srow] = xv0.z; Xs[0][skq + 3][srow] = xv0.w;
    Xs[0][skq + 0][srow + 64] = xv1.x; Xs[0][skq + 1][srow + 64] = xv1.y;
    Xs[0][skq + 2][srow + 64] = xv1.z; Xs[0][skq + 3][srow + 64] = xv1.w;
    Ws[0][skq + 0][srow] = wv.x; Ws[0][skq + 1][srow] = wv.y;
    Ws[0][skq + 2][srow] = wv.z; Ws[0][skq + 3][srow] = wv.w;
    __syncthreads();

    const int ntiles = K / 16;          // 64
#pragma unroll 1
    for (int it = 0; it < ntiles; it++) {
        const int buf = it & 1;
        if (it + 1 < ntiles) {
            xv0 = *reinterpret_cast<const float4*>(Xp0 + (it + 1) * 16);
            xv1 = *reinterpret_cast<const float4*>(Xp1 + (it + 1) * 16);
            wv  = *reinterpret_cast<const float4*>(Wp  + (it + 1) * 16);
        }
#pragma unroll
        for (int k = 0; k < 16; k++) {  // k strictly ascending
            const ulonglong2* ap =
                reinterpret_cast<const ulonglong2*>(&Xs[buf][k][ty * 8]);
            ulonglong2 a01 = ap[0];
            ulonglong2 a23 = ap[1];
            float4 b = *reinterpret_cast<const float4*>(&Ws[buf][k][tx * 4]);
            ull b2[4] = {pack2(b.x, b.x), pack2(b.y, b.y),
                         pack2(b.z, b.z), pack2(b.w, b.w)};
            ull a2[4] = {a01.x, a01.y, a23.x, a23.y};
#pragma unroll
            for (int u = 0; u < 4; u++)
#pragma unroll
                for (int j = 0; j < 4; j++)
                    fma2(acc2[u][j], a2[u], b2[j]);
        }
        if ((it + 1) * 16 == 512) {     // kc=512 panel boundary
#pragma unroll
            for (int u = 0; u < 4; u++)
#pragma unroll
                for (int j = 0; j < 4; j++) { accL2[u][j] = acc2[u][j]; acc2[u][j] = 0ull; }
        }
        if (it + 1 < ntiles) {
            const int nb = buf ^ 1;
            Xs[nb][skq + 0][srow] = xv0.x; Xs[nb][skq + 1][srow] = xv0.y;
            Xs[nb][skq + 2][srow] = xv0.z; Xs[nb][skq + 3][srow] = xv0.w;
            Xs[nb][skq + 0][srow + 64] = xv1.x; Xs[nb][skq + 1][srow + 64] = xv1.y;
            Xs[nb][skq + 2][srow + 64] = xv1.z; Xs[nb][skq + 3][srow + 64] = xv1.w;
            Ws[nb][skq + 0][srow] = wv.x; Ws[nb][skq + 1][srow] = wv.y;
            Ws[nb][skq + 2][srow] = wv.z; Ws[nb][skq + 3][srow] = wv.w;
        }
        __syncthreads();
    }

    float bv[4];
    if (EPI == 1) {
#pragma unroll
        for (int j = 0; j < 4; j++) bv[j] = bias[n0 + tx * 4 + j];
    }
#pragma unroll
    for (int u = 0; u < 4; u++) {
        float lo[4], hi[4];
#pragma unroll
        for (int j = 0; j < 4; j++) {
            ull s2 = add2(accL2[u][j], acc2[u][j]);   // add(chain_lo, chain_hi)
            unpack2(s2, lo[j], hi[j]);
            if (EPI == 1) {
                lo[j] = 1.f / (1.f + expf(-(lo[j] + bv[j])));
                hi[j] = 1.f / (1.f + expf(-(hi[j] + bv[j])));
            }
        }
        float4 o0; o0.x = lo[0]; o0.y = lo[1]; o0.z = lo[2]; o0.w = lo[3];
        float4 o1; o1.x = hi[0]; o1.y = hi[1]; o1.z = hi[2]; o1.w = hi[3];
        *reinterpret_cast<float4*>(
            out + (size_t)(m0 + ty * 8 + 2 * u) * N + n0 + tx * 4) = o0;
        *reinterpret_cast<float4*>(
            out + (size_t)(m0 + ty * 8 + 2 * u + 1) * N + n0 + tx * 4) = o1;
    }
}

// ---------------- persistent scan kernel v2: SMEM-staged, 512 threads ------
// grid = 128 CTAs x 512 threads. CTA owns 8 channels h0..h0+7.
// thread = (m, half, cg): m = tid&127, sub = tid>>7, half = sub&1 (k-half),
// cg = sub>>1 (channel quad). Each thread runs the k-ascending 512-term
// scalar FMA chain for 4 channels — per-channel chain bitwise == r13.
// Per step: 16 double-buffered phases; each phase cooperatively LDG->STS a
// 32-k slab of BOTH halves, compute from SMEM (LDS lat 29 cyc).
__global__ __launch_bounds__(512, 1) void scan_kernel(
    const float* __restrict__ state0, const float* __restrict__ A,
    const float* __restrict__ log_dt,
    const float* __restrict__ XB, const float* __restrict__ G,
    float* __restrict__ Sbuf, float* __restrict__ out_state)
{
    extern __shared__ float smem_dyn[];
    float* As = smem_dyn;                  // [HH][8]             8192 floats
    float* ss = smem_dyn + 8192;           // [2][2][32][128]    16384 floats
    float* Rs = smem_dyn + 8192 + 16384;   // [BB][9]             1152 floats

    const int tid  = threadIdx.x;
    const int bid  = blockIdx.x;
    const int h0   = bid * 8;
    const int m    = tid & 127;
    const int sub  = tid >> 7;             // 0..3
    const int half = sub & 1;              // k-half
    const int cg   = sub >> 1;             // channel quad (0 or 1)
    const int kbase = half * 512;
    const int ch0  = cg * 4;

    // stage A slice (coalesced along k)
    for (int idx = tid; idx < 8 * HH; idx += 512) {
        int j = idx >> 10, k = idx & 1023;
        As[k * 8 + j] = A[(size_t)(h0 + j) * HH + k];
    }
    // init k-major state
    if (tid < BB) {
#pragma unroll
        for (int j = 0; j < 8; j++)
            g_sT[0][h0 + j][tid] = state0[(size_t)tid * HH + h0 + j];
    }

    float dt[4], sreg[4];
    if (half == 0) {
#pragma unroll
        for (int j = 0; j < 4; j++) {
            float d = expf(log_dt[h0 + ch0 + j]);
            dt[j] = fminf(fmaxf(d, 0.001f), 0.1f);
            sreg[j] = state0[(size_t)m * HH + h0 + ch0 + j];
        }
    }

    unsigned gen = *(volatile unsigned*)&g_gen;
    gsync(bid, gen);

    const float* sbase = &g_sT[0][0][0];

    // cooperative-loader decomposition (fixed per thread): 4 float4 per phase
    int lf_hs[4], lf_kr[4], lf_mq[4];
#pragma unroll
    for (int i = 0; i < 4; i++) {
        int f = tid + i * 512;              // 0..2047
        lf_hs[i] = f >> 10;                 // which k-half
        int r = f & 1023;
        lf_kr[i] = r >> 5;                  // k row within slab (0..31)
        lf_mq[i] = r & 31;                  // m quad (0..31)
    }

    for (int t = 0; t < SS; t++) {
        const int cur = t & 1;
        const int nxt = cur ^ 1;
        const float* scur = sbase + (size_t)cur * HH * BB;

        float4 xb, gg;
        size_t rowbase = ((size_t)m * SS + t) * HH + h0 + ch0;
        if (half == 0) {
            xb = *reinterpret_cast<const float4*>(XB + rowbase);
            gg = *reinterpret_cast<const float4*>(G + rowbase);
        }

        float acc[4] = {0.f, 0.f, 0.f, 0.f};

        // ---- preload phase 0 slab ----
        float4 nv[4];
#pragma unroll
        for (int i = 0; i < 4; i++)
            nv[i] = __ldcg(reinterpret_cast<const float4*>(
                scur + (size_t)(lf_hs[i] * 512 + lf_kr[i]) * BB + lf_mq[i] * 4));
#pragma unroll
        for (int i = 0; i < 4; i++)
            *reinterpret_cast<float4*>(
                ss + ((size_t)lf_hs[i] * 32 + lf_kr[i]) * 128 + lf_mq[i] * 4) = nv[i];
        __syncthreads();

#pragma unroll 1
        for (int p = 0; p < 16; p++) {
            const int buf = p & 1;
            // LDG next slab early (covered by compute below)
            if (p < 15) {
#pragma unroll
                for (int i = 0; i < 4; i++)
                    nv[i] = __ldcg(reinterpret_cast<const float4*>(
                        scur + (size_t)(lf_hs[i] * 512 + (p + 1) * 32 + lf_kr[i]) * BB
                             + lf_mq[i] * 4));
            }
            // compute 32 k of this thread's half from SMEM (k ascending)
            const float* sscol = ss + ((size_t)(buf * 2 + half) * 32) * 128 + m;
            const float* arow  = As + (size_t)(kbase + p * 32) * 8 + ch0;
#pragma unroll
            for (int k = 0; k < 32; k++) {
                float sv = sscol[k * 128];
                float4 aq = *reinterpret_cast<const float4*>(arow + k * 8);
                acc[0] = fmaf(sv, aq.x, acc[0]);
                acc[1] = fmaf(sv, aq.y, acc[1]);
                acc[2] = fmaf(sv, aq.z, acc[2]);
                acc[3] = fmaf(sv, aq.w, acc[3]);
            }
            // store next slab into the other buffer
            if (p < 15) {
                const int nb = buf ^ 1;
#pragma unroll
                for (int i = 0; i < 4; i++)
                    *reinterpret_cast<float4*>(
                        ss + ((size_t)(nb * 2 + lf_hs[i]) * 32 + lf_kr[i]) * 128
                           + lf_mq[i] * 4) = nv[i];
            }
            __syncthreads();
        }

        if (half == 1) {
#pragma unroll
            for (int j = 0; j < 4; j++) Rs[m * 9 + ch0 + j] = acc[j];
        }
        __syncthreads();

        if (half == 0) {
            float xbv[4] = {xb.x, xb.y, xb.z, xb.w};
            float ggv[4] = {gg.x, gg.y, gg.z, gg.w};
            float sn[4];
#pragma unroll
            for (int j = 0; j < 4; j++) {
                float dstate = acc[j] + Rs[m * 9 + ch0 + j] + xbv[j];  // (lo+hi)+xb
                float sc = dstate * dt[j];
                if (fabsf(sc) <= 0.1f) sc = 0.f;
                float v = sreg[j] + sc * ggv[j];            // default contraction
                sreg[j] = v;
                sn[j] = v;
                g_sT[nxt][h0 + ch0 + j][m] = v;             // coalesced across m
            }
            float4 o; o.x = sn[0]; o.y = sn[1]; o.z = sn[2]; o.w = sn[3];
            *reinterpret_cast<float4*>(Sbuf + rowbase) = o;
            if (t == SS - 1 && out_state != nullptr) {
#pragma unroll
                for (int j = 0; j < 4; j++)
                    out_state[(size_t)m * HH + h0 + ch0 + j] = sn[j];
            }
        }

        gsync(bid, gen);
    }
}

// ---------------- launch ----------------------------------------------------
extern "C" void kernel_launch(void* const* d_in, const int* in_sizes, int n_in,
                              void* d_out, int out_size) {
    const float* x      = (const float*)d_in[0];
    const float* state  = (const float*)d_in[1];
    const float* A      = (const float*)d_in[2];
    const float* Bm     = (const float*)d_in[3];
    const float* C      = (const float*)d_in[4];
    const float* log_dt = (const float*)d_in[5];
    const float* Wg     = (const float*)d_in[6];
    const float* bg     = (const float*)d_in[7];

    float* ys = (float*)d_out;
    const size_t ys_elems = (size_t)BB * SS * HH;
    float* out_state = nullptr;
    if ((size_t)out_size >= ys_elems + (size_t)BB * HH)
        out_state = ys + ys_elems;

    float *pXB = nullptr, *pG = nullptr, *pS = nullptr;
    cudaGetSymbolAddress((void**)&pXB, g_XB);
    cudaGetSymbolAddress((void**)&pG,  g_G);
    cudaGetSymbolAddress((void**)&pS,  g_Sbuf);

    const int M = BB * SS;            // 65536
    dim3 grid(HH / 64, M / 128);      // (16, 512), n fastest

    const int SCAN_SMEM = (8192 + 16384 + 1152) * 4;   // 102912 B
    cudaFuncSetAttribute(scan_kernel,
                         cudaFuncAttributeMaxDynamicSharedMemorySize, SCAN_SMEM);

    // off-critical-path GEMMs (kc=512 blocked chains, bitwise == round 10)
    sgemm_nt<0><<<grid, 256>>>(x, Bm, nullptr, pXB, M, HH, HH);
    sgemm_nt<1><<<grid, 256>>>(x, Wg, bg,      pG,  M, HH, HH);

    // sequential scan (persistent, 128 CTAs x 512 threads, SMEM-staged)
    scan_kernel<<<BB, 512, SCAN_SMEM>>>(state, A, log_dt, pXB, pG, pS, out_state);

    // y = Sbuf @ C^T (kc=512 blocked chains)
    sgemm_nt<0><<<grid, 256>>>(pS, C, nullptr, ys, M, HH, HH);
}